// round 13
// baseline (speedup 1.0000x reference)
#include <cuda_runtime.h>
#include <cuda_fp16.h>
#include <math.h>
#include <stdint.h>

#define BDIM 8192
#define HDIM 2048
#define TOPK 32
#define CAND 48
#define LCAP 3072
#define FCAP 128
#define DELTA 5e-5f
#define NEGINF (-INFINITY)

// ---- GEMM tiling ----
#define KCHUNK 64
#define NKC (HDIM / KCHUNK)
#define TILE_M 128
#define NRB (BDIM / TILE_M)
#define TILE_ELEMS (TILE_M * KCHUNK)
#define TILE_BYTES (TILE_ELEMS * 2)
#define STAGES 3
#define STAGE_BYTES (2 * TILE_BYTES)
#define SMEM_TOTAL (STAGES * STAGE_BYTES)

// ---- topk ----
#define TK_DSMEM (BDIM * 4)              // 32 KB key cache

// ---- device scratch ----
__device__ float g_sim[(size_t)BDIM * BDIM];
__device__ float g_invn[BDIM];
__device__ int   g_topidx[BDIM * TOPK];
__device__ float g_topw[BDIM * TOPK];
__device__ __half g_hi[(size_t)NKC * NRB * TILE_ELEMS];

// ==================== asm helpers ====================
__device__ __forceinline__ uint32_t smem_u32(const void* p) {
    uint32_t a;
    asm("{ .reg .u64 t; cvta.to.shared.u64 t, %1; cvt.u32.u64 %0, t; }" : "=r"(a) : "l"(p));
    return a;
}

#define CP16(dst, src) \
    asm volatile("cp.async.cg.shared.global [%0], [%1], 16;" :: "r"(dst), "l"(src) : "memory")
#define CPCOMMIT() asm volatile("cp.async.commit_group;" ::: "memory")
#define CPWAIT1()  asm volatile("cp.async.wait_group 1;" ::: "memory")
#define CPWAIT0()  asm volatile("cp.async.wait_group 0;" ::: "memory")

#define LDSM4(r0, r1, r2, r3, addr) \
    asm volatile("ldmatrix.sync.aligned.m8n8.x4.shared.b16 {%0,%1,%2,%3}, [%4];" \
        : "=r"(r0), "=r"(r1), "=r"(r2), "=r"(r3) : "r"(addr))

#define MMA16816(d, a, b) \
    asm volatile("mma.sync.aligned.m16n8k16.row.col.f32.f16.f16.f32 " \
        "{%0,%1,%2,%3}, {%4,%5,%6,%7}, {%8,%9}, {%0,%1,%2,%3};" \
        : "+f"((d)[0]), "+f"((d)[1]), "+f"((d)[2]), "+f"((d)[3]) \
        : "r"((a)[0]), "r"((a)[1]), "r"((a)[2]), "r"((a)[3]), "r"((b)[0]), "r"((b)[1]))

// ==================== K0: fused norms + fp16 swizzled prep (one block per row) ====================
__global__ __launch_bounds__(256) void prep_norms_kernel(const float* __restrict__ hs) {
    const int r = blockIdx.x;
    const int tid = threadIdx.x;
    const float* p = hs + (size_t)r * HDIM;
    const int rb = r >> 7, rr = r & 127;
    float ssq = 0.f;

    #pragma unroll
    for (int half = 0; half < 2; half++) {
        int k4 = tid * 4 + half * 1024;
        float4 v = *(const float4*)(p + k4);
        float vv[4] = {v.x, v.y, v.z, v.w};
        int kc = k4 >> 6;
        size_t base = ((size_t)(kc * NRB + rb)) * TILE_ELEMS;
        #pragma unroll
        for (int j = 0; j < 4; j++) {
            float f = vv[j];
            ssq = fmaf(f, f, ssq);
            int c = (k4 + j) & 63;
            uint32_t off = (uint32_t)(rr * 128 + c * 2);
            uint32_t sw  = (off ^ (((uint32_t)(rr & 7)) << 4)) >> 1;
            g_hi[base + sw] = __float2half(f);
        }
    }

    __shared__ float red[8];
    for (int o = 16; o; o >>= 1) ssq += __shfl_down_sync(0xffffffffu, ssq, o);
    if ((tid & 31) == 0) red[tid >> 5] = ssq;
    __syncthreads();
    if (tid == 0) {
        float v = 0.f;
        for (int i = 0; i < 8; i++) v += red[i];
        g_invn[r] = 1.0f / fmaxf(sqrtf(v), 1e-12f);
    }
}

// ==================== K2: sim ~= H H^T via fp16 mma.sync, symmetric ====================
__global__ __launch_bounds__(256, 2) void simgemm_mma(const int* __restrict__ mask) {
    const int bj = blockIdx.x, bi = blockIdx.y;
    if (bi > bj) return;
    extern __shared__ __align__(128) char smem[];
    const uint32_t sbase = smem_u32(smem);
    const int tid = threadIdx.x;
    const int lane = tid & 31, wid = tid >> 5;
    const int wm = wid & 1, wn = wid >> 1;

    float acc[4][4][4];
    #pragma unroll
    for (int a = 0; a < 4; a++)
        #pragma unroll
        for (int b = 0; b < 4; b++)
            #pragma unroll
            for (int c = 0; c < 4; c++) acc[a][b][c] = 0.f;

    const __half* baseA = g_hi + (size_t)bi * TILE_ELEMS;
    const __half* baseB = g_hi + (size_t)bj * TILE_ELEMS;
    const size_t kc_stride = (size_t)NRB * TILE_ELEMS;

    const int rbase = (lane & 7) + ((lane >> 3) & 1) * 8;
    const int csel  = lane >> 4;

    auto issue = [&](int kc, int s) {
        uint32_t sb = sbase + s * STAGE_BYTES;
        const char* sa  = (const char*)(baseA + (size_t)kc * kc_stride);
        const char* sbp = (const char*)(baseB + (size_t)kc * kc_stride);
        #pragma unroll
        for (int i = 0; i < 4; i++) {
            uint32_t o = (uint32_t)(tid * 16 + i * 4096);
            CP16(sb + o, sa + o);
            CP16(sb + TILE_BYTES + o, sbp + o);
        }
        CPCOMMIT();
    };

    issue(0, 0);
    issue(1, 1);

    for (int kc = 0; kc < NKC; kc++) {
        CPWAIT1();
        __syncthreads();
        if (kc + 2 < NKC) issue(kc + 2, (kc + 2) % STAGES);

        uint32_t sb = sbase + (kc % STAGES) * STAGE_BYTES;
        #pragma unroll
        for (int k16 = 0; k16 < 4; k16++) {
            uint32_t ah[4][4], bh[4][2];
            #pragma unroll
            for (int mt = 0; mt < 4; mt++) {
                int row = wm * 64 + mt * 16 + rbase;
                uint32_t off = (uint32_t)(row * 128 + (((k16 * 2 + csel) ^ (row & 7)) * 16));
                LDSM4(ah[mt][0], ah[mt][1], ah[mt][2], ah[mt][3], sb + off);
            }
            #pragma unroll
            for (int p = 0; p < 2; p++) {
                int row = wn * 32 + p * 16 + rbase;
                uint32_t off = (uint32_t)(row * 128 + (((k16 * 2 + csel) ^ (row & 7)) * 16));
                uint32_t r0, r1, r2, r3;
                LDSM4(r0, r1, r2, r3, sb + TILE_BYTES + off);
                bh[2*p][0] = r0; bh[2*p][1] = r2; bh[2*p+1][0] = r1; bh[2*p+1][1] = r3;
            }
            #pragma unroll
            for (int mt = 0; mt < 4; mt++)
                #pragma unroll
                for (int nt = 0; nt < 4; nt++)
                    MMA16816(acc[mt][nt], ah[mt], bh[nt]);
        }
    }
    CPWAIT0();

    const int i0 = bi * 128 + wm * 64;
    const int j0 = bj * 128 + wn * 32;
    const int grp = lane >> 2, qd = lane & 3;
    #pragma unroll
    for (int mt = 0; mt < 4; mt++) {
        #pragma unroll
        for (int half = 0; half < 2; half++) {
            int row = i0 + mt * 16 + grp + half * 8;
            float sa = g_invn[row];
            int mr = mask[row];
            #pragma unroll
            for (int nt = 0; nt < 4; nt++) {
                int col = j0 + nt * 8 + qd * 2;
                float v0 = acc[mt][nt][half * 2 + 0] * sa * g_invn[col];
                float v1 = acc[mt][nt][half * 2 + 1] * sa * g_invn[col + 1];
                float2 o;
                o.x = (row == col     || mask[col]     == 0) ? NEGINF : v0;
                o.y = (row == col + 1 || mask[col + 1] == 0) ? NEGINF : v1;
                *(float2*)(g_sim + (size_t)row * BDIM + col) = o;
                if (bi != bj) {
                    g_sim[(size_t)col * BDIM + row]       = mr ? v0 : NEGINF;
                    g_sim[(size_t)(col + 1) * BDIM + row] = mr ? v1 : NEGINF;
                }
            }
        }
    }
}

// ==================== K3: per-row top-32, radix select (smem key cache) + windowed fixup ====================
__device__ __forceinline__ uint32_t f2key(float f) {
    uint32_t b = __float_as_uint(f);
    return (b & 0x80000000u) ? ~b : (b | 0x80000000u);
}
__device__ __forceinline__ float key2f(uint32_t k) {
    return __uint_as_float((k & 0x80000000u) ? (k & 0x7FFFFFFFu) : ~k);
}

__global__ __launch_bounds__(256) void topk_kernel(const float* __restrict__ hs) {
    extern __shared__ __align__(16) uint32_t skey[];    // 8192 keys (32 KB dynamic)
    __shared__ int whist[8][256];
    __shared__ int hist[256];
    __shared__ int sbin0, srem0, sbin1, srem1, scnt, sfin, sd, su;
    __shared__ uint32_t lkey[LCAP];
    __shared__ uint16_t lidx[LCAP];
    __shared__ uint32_t fkey[FCAP];
    __shared__ int      fidx[FCAP];
    __shared__ float svals[FCAP];
    __shared__ int   sidxs[FCAP];
    __shared__ float exv[FCAP];
    const int row = blockIdx.x;
    const int tid = threadIdx.x, wid = tid >> 5, lid = tid & 31;
    const float* sp = g_sim + (size_t)row * BDIM;

    // ---- pass A: stream row once; transform -> smem keys; per-warp private hists ----
    {
        int* wh = &whist[0][0];
        for (int i = tid; i < 8 * 256; i += 256) wh[i] = 0;
    }
    __syncthreads();
    for (int c0 = tid * 4; c0 < BDIM; c0 += 1024) {
        float4 v = *(const float4*)(sp + c0);
        const float* vp = &v.x;
        #pragma unroll
        for (int j = 0; j < 4; j++) {
            uint32_t k = f2key(vp[j]);
            skey[c0 + j] = k;
            uint32_t bin = k >> 24;
            uint32_t mg = __match_any_sync(0xffffffffu, bin);
            if (lid == __ffs(mg) - 1) whist[wid][bin] += __popc(mg);
        }
    }
    __syncthreads();
    {
        int t = 0;
        #pragma unroll
        for (int w = 0; w < 8; w++) t += whist[w][tid];
        hist[tid] = t;
    }
    __syncthreads();
    if (tid < 32) {
        int b0 = 248 - 8 * tid;
        int h[8], part = 0;
        #pragma unroll
        for (int q = 0; q < 8; q++) { h[q] = hist[b0 + q]; part += h[q]; }
        int inc = part;
        #pragma unroll
        for (int o = 1; o < 32; o <<= 1) {
            int t = __shfl_up_sync(0xffffffffu, inc, o);
            if (tid >= o) inc += t;
        }
        int pre = inc - part;
        if (pre < CAND && CAND <= inc) {
            int c = pre;
            #pragma unroll
            for (int q = 7; q >= 0; q--) {
                int nb = c + h[q];
                if (nb >= CAND) { sbin0 = b0 + q; srem0 = CAND - c; break; }
                c = nb;
            }
        }
    }
    if (tid == 0) scnt = 0;
    __syncthreads();
    const uint32_t bound0 = (uint32_t)sbin0 << 24;
    const int rem0 = srem0;

    // ---- pass B: gather candidates from smem keys (warp-aggregated) ----
    for (int c = tid; c < BDIM; c += 256) {
        uint32_t k = skey[c];
        bool pred = (k >= bound0);
        uint32_t bal = __ballot_sync(0xffffffffu, pred);
        if (bal) {
            int leader = __ffs(bal) - 1;
            int b0v = 0;
            if (lid == leader) b0v = atomicAdd(&scnt, __popc(bal));
            b0v = __shfl_sync(0xffffffffu, b0v, leader);
            if (pred) {
                int p = b0v + __popc(bal & ((1u << lid) - 1u));
                if (p < LCAP) { lkey[p] = k; lidx[p] = (uint16_t)c; }
            }
        }
    }
    __syncthreads();
    const int n = (scnt < LCAP) ? scnt : LCAP;

    // ---- level 1 on compact list ----
    hist[tid] = 0;
    __syncthreads();
    for (int i = tid; i < n; i += 256) {
        uint32_t k = lkey[i];
        if ((k >> 24) == (uint32_t)sbin0) atomicAdd(&hist[(k >> 16) & 255u], 1);
    }
    __syncthreads();
    if (tid < 32) {
        int b0 = 248 - 8 * tid;
        int h[8], part = 0;
        #pragma unroll
        for (int q = 0; q < 8; q++) { h[q] = hist[b0 + q]; part += h[q]; }
        int inc = part;
        #pragma unroll
        for (int o = 1; o < 32; o <<= 1) {
            int t = __shfl_up_sync(0xffffffffu, inc, o);
            if (tid >= o) inc += t;
        }
        int pre = inc - part;
        if (pre < rem0 && rem0 <= inc) {
            int c = pre;
            #pragma unroll
            for (int q = 7; q >= 0; q--) {
                int nb = c + h[q];
                if (nb >= rem0) { sbin1 = b0 + q; srem1 = rem0 - c; break; }
                c = nb;
            }
        }
    }
    if (tid == 0) sfin = 0;
    __syncthreads();
    const uint32_t prefix16 = ((uint32_t)sbin0 << 8) | (uint32_t)sbin1;

    // ---- final gather ----
    for (int i = tid; i < n; i += 256) {
        uint32_t k = lkey[i];
        if ((k >> 16) >= prefix16) {
            int p = atomicAdd(&sfin, 1);
            if (p < FCAP) { fkey[p] = k; fidx[p] = (int)lidx[i]; }
        }
    }
    __syncthreads();
    const int m = (sfin < FCAP) ? sfin : FCAP;

    // ---- rank sort descending (stable by index) ----
    if (tid < m) {
        uint32_t k = fkey[tid]; int ix = fidx[tid];
        int r = 0;
        for (int j = 0; j < m; j++) {
            uint32_t kj = fkey[j];
            if (kj > k || (kj == k && fidx[j] < ix)) r++;
        }
        if (r < FCAP) { svals[r] = key2f(k); sidxs[r] = ix; }
    }
    __syncthreads();

    // ---- windowed exact-fp32 fixup around rank-32 ----
    if (tid == 0) {
        float t32 = svals[TOPK - 1];
        float hi = t32 + DELTA, lo = t32 - DELTA;
        int d = 0;
        while (d < TOPK && svals[d] > hi) d++;
        int u = 0;
        while (d + u < m && svals[d + u] >= lo) u++;
        sd = d; su = u;
    }
    __syncthreads();
    const int d = sd, u = su;
    if (u > 0 && d < TOPK) {
        const float* hrow = hs + (size_t)row * HDIM;
        const float inr = g_invn[row];
        for (int p = d + wid; p < d + u; p += 8) {
            const float* hc = hs + (size_t)sidxs[p] * HDIM;
            float acc = 0.f;
            for (int q = lid; q < HDIM; q += 32) acc = fmaf(hrow[q], hc[q], acc);
            #pragma unroll
            for (int o = 16; o; o >>= 1) acc += __shfl_down_sync(0xffffffffu, acc, o);
            if (lid == 0) exv[p] = acc * inr * g_invn[sidxs[p]];
        }
        __syncthreads();
        if (tid == 0) {
            float cv[FCAP]; int ci[FCAP]; bool used[FCAP];
            for (int p = 0; p < u; p++) { cv[p] = exv[d + p]; ci[p] = sidxs[d + p]; used[p] = false; }
            int pick = TOPK - d;
            if (pick > u) pick = u;
            for (int s = 0; s < pick; s++) {
                float bv = NEGINF; int bp = -1;
                for (int p = 0; p < u; p++)
                    if (!used[p] && (bp < 0 || cv[p] > bv)) { bv = cv[p]; bp = p; }
                used[bp] = true;
                svals[d + s] = bv; sidxs[d + s] = ci[bp];
            }
        }
        __syncthreads();
    }

    // ---- softmax over top-32 ----
    if (tid < TOPK) {
        float v = svals[tid];
        float mx = v;
        #pragma unroll
        for (int o = 16; o; o >>= 1) mx = fmaxf(mx, __shfl_xor_sync(0xffffffffu, mx, o));
        float e = isfinite(v) ? __expf(v - mx) : 0.f;
        float s = e;
        #pragma unroll
        for (int o = 16; o; o >>= 1) s += __shfl_xor_sync(0xffffffffu, s, o);
        float w = (s > 0.f) ? e / s : 0.f;
        g_topw[row * TOPK + tid] = w;
        g_topidx[row * TOPK + tid] = sidxs[tid];
    }
}

// ==================== K4: sparse cross + gate + residual ====================
__global__ __launch_bounds__(256) void cross_gate_kernel(const float* __restrict__ hs,
                                                         const float* __restrict__ gw,
                                                         const float* __restrict__ gb,
                                                         float* __restrict__ out) {
    const int row = blockIdx.x;
    const int tid = threadIdx.x;
    __shared__ float sw[TOPK];
    __shared__ int   si[TOPK];
    __shared__ float red[8];
    __shared__ float gsh;
    if (tid < TOPK) { sw[tid] = g_topw[row * TOPK + tid]; si[tid] = g_topidx[row * TOPK + tid]; }
    __syncthreads();

    float cr[HDIM / 256];
    float p = 0.f;
    #pragma unroll
    for (int u = 0; u < HDIM / 256; u++) {
        int c = tid + u * 256;
        float acc = 0.f;
        #pragma unroll
        for (int k = 0; k < TOPK; k++)
            acc = fmaf(sw[k], hs[(size_t)si[k] * HDIM + c], acc);
        cr[u] = acc;
        float h = hs[(size_t)row * HDIM + c];
        p = fmaf(gw[c], h, p);
        p = fmaf(gw[HDIM + c], acc, p);
    }
    for (int o = 16; o; o >>= 1) p += __shfl_down_sync(0xffffffffu, p, o);
    if ((tid & 31) == 0) red[tid >> 5] = p;
    __syncthreads();
    if (tid == 0) {
        float v = 0.f;
        for (int i = 0; i < 8; i++) v += red[i];
        gsh = 1.f / (1.f + __expf(-(v + gb[0])));
    }
    __syncthreads();
    float g = gsh;
    #pragma unroll
    for (int u = 0; u < HDIM / 256; u++) {
        int c = tid + u * 256;
        float h = hs[(size_t)row * HDIM + c];
        out[(size_t)row * HDIM + c] = h + g * cr[u];
    }
}

// ==================== launch ====================
extern "C" void kernel_launch(void* const* d_in, const int* in_sizes, int n_in,
                              void* d_out, int out_size) {
    const float* hs  = (const float*)d_in[0];
    const int*   msk = (const int*)d_in[1];
    const float* gw  = (const float*)d_in[2];
    const float* gb  = (const float*)d_in[3];
    float* out       = (float*)d_out;

    static int smem_set = 0;
    if (!smem_set) {
        cudaFuncSetAttribute(simgemm_mma, cudaFuncAttributeMaxDynamicSharedMemorySize, SMEM_TOTAL);
        cudaFuncSetAttribute(topk_kernel, cudaFuncAttributeMaxDynamicSharedMemorySize, TK_DSMEM);
        smem_set = 1;
    }

    prep_norms_kernel<<<BDIM, 256>>>(hs);
    dim3 grid(NRB, NRB);
    simgemm_mma<<<grid, 256, SMEM_TOTAL>>>(msk);
    topk_kernel<<<BDIM, 256, TK_DSMEM>>>(hs);
    cross_gate_kernel<<<BDIM, 256>>>(hs, gw, gb, out);
}

// round 14
// speedup vs baseline: 1.2757x; 1.2757x over previous
#include <cuda_runtime.h>
#include <cuda_fp16.h>
#include <math.h>
#include <stdint.h>

#define BDIM 8192
#define HDIM 2048
#define TOPK 32
#define CAND 48
#define LCAP 3072
#define FCAP 128
#define DELTA 5e-5f
#define NEGINF (-INFINITY)

// ---- GEMM tiling ----
#define KCHUNK 64
#define NKC (HDIM / KCHUNK)
#define TILE_M 128
#define NRB (BDIM / TILE_M)
#define TILE_ELEMS (TILE_M * KCHUNK)
#define TILE_BYTES (TILE_ELEMS * 2)
#define STAGES 3
#define STAGE_BYTES (2 * TILE_BYTES)
#define SMEM_TOTAL (STAGES * STAGE_BYTES)

// ---- device scratch ----
__device__ float g_sim[(size_t)BDIM * BDIM];
__device__ float g_invn[BDIM];
__device__ int   g_topidx[BDIM * TOPK];
__device__ float g_topw[BDIM * TOPK];
__device__ __half g_hi[(size_t)NKC * NRB * TILE_ELEMS];

// ==================== asm helpers ====================
__device__ __forceinline__ uint32_t smem_u32(const void* p) {
    uint32_t a;
    asm("{ .reg .u64 t; cvta.to.shared.u64 t, %1; cvt.u32.u64 %0, t; }" : "=r"(a) : "l"(p));
    return a;
}

#define CP16(dst, src) \
    asm volatile("cp.async.cg.shared.global [%0], [%1], 16;" :: "r"(dst), "l"(src) : "memory")
#define CPCOMMIT() asm volatile("cp.async.commit_group;" ::: "memory")
#define CPWAIT1()  asm volatile("cp.async.wait_group 1;" ::: "memory")
#define CPWAIT0()  asm volatile("cp.async.wait_group 0;" ::: "memory")

#define LDSM4(r0, r1, r2, r3, addr) \
    asm volatile("ldmatrix.sync.aligned.m8n8.x4.shared.b16 {%0,%1,%2,%3}, [%4];" \
        : "=r"(r0), "=r"(r1), "=r"(r2), "=r"(r3) : "r"(addr))

#define MMA16816(d, a, b) \
    asm volatile("mma.sync.aligned.m16n8k16.row.col.f32.f16.f16.f32 " \
        "{%0,%1,%2,%3}, {%4,%5,%6,%7}, {%8,%9}, {%0,%1,%2,%3};" \
        : "+f"((d)[0]), "+f"((d)[1]), "+f"((d)[2]), "+f"((d)[3]) \
        : "r"((a)[0]), "r"((a)[1]), "r"((a)[2]), "r"((a)[3]), "r"((b)[0]), "r"((b)[1]))

// ==================== K0: fused norms + fp16 swizzled prep (one block per row) ====================
__global__ __launch_bounds__(256) void prep_norms_kernel(const float* __restrict__ hs) {
    const int r = blockIdx.x;
    const int tid = threadIdx.x;
    const float* p = hs + (size_t)r * HDIM;
    const int rb = r >> 7, rr = r & 127;
    float ssq = 0.f;

    #pragma unroll
    for (int half = 0; half < 2; half++) {
        int k4 = tid * 4 + half * 1024;
        float4 v = *(const float4*)(p + k4);
        float vv[4] = {v.x, v.y, v.z, v.w};
        int kc = k4 >> 6;
        size_t base = ((size_t)(kc * NRB + rb)) * TILE_ELEMS;
        #pragma unroll
        for (int j = 0; j < 4; j++) {
            float f = vv[j];
            ssq = fmaf(f, f, ssq);
            int c = (k4 + j) & 63;
            uint32_t off = (uint32_t)(rr * 128 + c * 2);
            uint32_t sw  = (off ^ (((uint32_t)(rr & 7)) << 4)) >> 1;
            g_hi[base + sw] = __float2half(f);
        }
    }

    __shared__ float red[8];
    for (int o = 16; o; o >>= 1) ssq += __shfl_down_sync(0xffffffffu, ssq, o);
    if ((tid & 31) == 0) red[tid >> 5] = ssq;
    __syncthreads();
    if (tid == 0) {
        float v = 0.f;
        for (int i = 0; i < 8; i++) v += red[i];
        g_invn[r] = 1.0f / fmaxf(sqrtf(v), 1e-12f);
    }
}

// ==================== K2: sim ~= H H^T via fp16 mma.sync, symmetric ====================
__global__ __launch_bounds__(256, 2) void simgemm_mma(const int* __restrict__ mask) {
    const int bj = blockIdx.x, bi = blockIdx.y;
    if (bi > bj) return;
    extern __shared__ __align__(128) char smem[];
    const uint32_t sbase = smem_u32(smem);
    const int tid = threadIdx.x;
    const int lane = tid & 31, wid = tid >> 5;
    const int wm = wid & 1, wn = wid >> 1;

    float acc[4][4][4];
    #pragma unroll
    for (int a = 0; a < 4; a++)
        #pragma unroll
        for (int b = 0; b < 4; b++)
            #pragma unroll
            for (int c = 0; c < 4; c++) acc[a][b][c] = 0.f;

    const __half* baseA = g_hi + (size_t)bi * TILE_ELEMS;
    const __half* baseB = g_hi + (size_t)bj * TILE_ELEMS;
    const size_t kc_stride = (size_t)NRB * TILE_ELEMS;

    const int rbase = (lane & 7) + ((lane >> 3) & 1) * 8;
    const int csel  = lane >> 4;

    auto issue = [&](int kc, int s) {
        uint32_t sb = sbase + s * STAGE_BYTES;
        const char* sa  = (const char*)(baseA + (size_t)kc * kc_stride);
        const char* sbp = (const char*)(baseB + (size_t)kc * kc_stride);
        #pragma unroll
        for (int i = 0; i < 4; i++) {
            uint32_t o = (uint32_t)(tid * 16 + i * 4096);
            CP16(sb + o, sa + o);
            CP16(sb + TILE_BYTES + o, sbp + o);
        }
        CPCOMMIT();
    };

    issue(0, 0);
    issue(1, 1);

    for (int kc = 0; kc < NKC; kc++) {
        CPWAIT1();
        __syncthreads();
        if (kc + 2 < NKC) issue(kc + 2, (kc + 2) % STAGES);

        uint32_t sb = sbase + (kc % STAGES) * STAGE_BYTES;
        #pragma unroll
        for (int k16 = 0; k16 < 4; k16++) {
            uint32_t ah[4][4], bh[4][2];
            #pragma unroll
            for (int mt = 0; mt < 4; mt++) {
                int row = wm * 64 + mt * 16 + rbase;
                uint32_t off = (uint32_t)(row * 128 + (((k16 * 2 + csel) ^ (row & 7)) * 16));
                LDSM4(ah[mt][0], ah[mt][1], ah[mt][2], ah[mt][3], sb + off);
            }
            #pragma unroll
            for (int p = 0; p < 2; p++) {
                int row = wn * 32 + p * 16 + rbase;
                uint32_t off = (uint32_t)(row * 128 + (((k16 * 2 + csel) ^ (row & 7)) * 16));
                uint32_t r0, r1, r2, r3;
                LDSM4(r0, r1, r2, r3, sb + TILE_BYTES + off);
                bh[2*p][0] = r0; bh[2*p][1] = r2; bh[2*p+1][0] = r1; bh[2*p+1][1] = r3;
            }
            #pragma unroll
            for (int mt = 0; mt < 4; mt++)
                #pragma unroll
                for (int nt = 0; nt < 4; nt++)
                    MMA16816(acc[mt][nt], ah[mt], bh[nt]);
        }
    }
    CPWAIT0();

    const int i0 = bi * 128 + wm * 64;
    const int j0 = bj * 128 + wn * 32;
    const int grp = lane >> 2, qd = lane & 3;
    #pragma unroll
    for (int mt = 0; mt < 4; mt++) {
        #pragma unroll
        for (int half = 0; half < 2; half++) {
            int row = i0 + mt * 16 + grp + half * 8;
            float sa = g_invn[row];
            int mr = mask[row];
            #pragma unroll
            for (int nt = 0; nt < 4; nt++) {
                int col = j0 + nt * 8 + qd * 2;
                float v0 = acc[mt][nt][half * 2 + 0] * sa * g_invn[col];
                float v1 = acc[mt][nt][half * 2 + 1] * sa * g_invn[col + 1];
                float2 o;
                o.x = (row == col     || mask[col]     == 0) ? NEGINF : v0;
                o.y = (row == col + 1 || mask[col + 1] == 0) ? NEGINF : v1;
                *(float2*)(g_sim + (size_t)row * BDIM + col) = o;
                if (bi != bj) {
                    g_sim[(size_t)col * BDIM + row]       = mr ? v0 : NEGINF;
                    g_sim[(size_t)(col + 1) * BDIM + row] = mr ? v1 : NEGINF;
                }
            }
        }
    }
}

// ==================== K3: per-row top-32, radix select + windowed fixup (R10 verbatim) ====================
__device__ __forceinline__ uint32_t f2key(float f) {
    uint32_t b = __float_as_uint(f);
    return (b & 0x80000000u) ? ~b : (b | 0x80000000u);
}
__device__ __forceinline__ float key2f(uint32_t k) {
    return __uint_as_float((k & 0x80000000u) ? (k & 0x7FFFFFFFu) : ~k);
}

__global__ __launch_bounds__(256) void topk_kernel(const float* __restrict__ hs) {
    __shared__ int whist[8][256];
    __shared__ int hist[256];
    __shared__ int sbin0, srem0, sbin1, srem1, scnt, sfin, sd, su;
    __shared__ uint32_t lkey[LCAP];
    __shared__ uint16_t lidx[LCAP];
    __shared__ uint32_t fkey[FCAP];
    __shared__ int      fidx[FCAP];
    __shared__ float svals[FCAP];
    __shared__ int   sidxs[FCAP];
    __shared__ float exv[FCAP];
    const int row = blockIdx.x;
    const int tid = threadIdx.x, wid = tid >> 5, lid = tid & 31;
    const float* sp = g_sim + (size_t)row * BDIM;

    {
        int* wh = &whist[0][0];
        for (int i = tid; i < 8 * 256; i += 256) wh[i] = 0;
    }
    __syncthreads();
    for (int c0 = tid * 4; c0 < BDIM; c0 += 1024) {
        float4 v = *(const float4*)(sp + c0);
        const float* vp = &v.x;
        #pragma unroll
        for (int j = 0; j < 4; j++) {
            uint32_t bin = f2key(vp[j]) >> 24;
            uint32_t mg = __match_any_sync(0xffffffffu, bin);
            if (lid == __ffs(mg) - 1) whist[wid][bin] += __popc(mg);
        }
    }
    __syncthreads();
    {
        int t = 0;
        #pragma unroll
        for (int w = 0; w < 8; w++) t += whist[w][tid];
        hist[tid] = t;
    }
    __syncthreads();
    if (tid < 32) {
        int b0 = 248 - 8 * tid;
        int h[8], part = 0;
        #pragma unroll
        for (int q = 0; q < 8; q++) { h[q] = hist[b0 + q]; part += h[q]; }
        int inc = part;
        #pragma unroll
        for (int o = 1; o < 32; o <<= 1) {
            int t = __shfl_up_sync(0xffffffffu, inc, o);
            if (tid >= o) inc += t;
        }
        int pre = inc - part;
        if (pre < CAND && CAND <= inc) {
            int c = pre;
            #pragma unroll
            for (int q = 7; q >= 0; q--) {
                int nb = c + h[q];
                if (nb >= CAND) { sbin0 = b0 + q; srem0 = CAND - c; break; }
                c = nb;
            }
        }
    }
    if (tid == 0) scnt = 0;
    __syncthreads();
    const uint32_t bound0 = (uint32_t)sbin0 << 24;
    const int rem0 = srem0;

    for (int c0 = tid * 4; c0 < BDIM; c0 += 1024) {
        float4 v = *(const float4*)(sp + c0);
        const float* vp = &v.x;
        #pragma unroll
        for (int j = 0; j < 4; j++) {
            uint32_t k = f2key(vp[j]);
            bool pred = (k >= bound0);
            uint32_t bal = __ballot_sync(0xffffffffu, pred);
            if (bal) {
                int leader = __ffs(bal) - 1;
                int b0v = 0;
                if (lid == leader) b0v = atomicAdd(&scnt, __popc(bal));
                b0v = __shfl_sync(0xffffffffu, b0v, leader);
                if (pred) {
                    int p = b0v + __popc(bal & ((1u << lid) - 1u));
                    if (p < LCAP) { lkey[p] = k; lidx[p] = (uint16_t)(c0 + j); }
                }
            }
        }
    }
    __syncthreads();
    const int n = (scnt < LCAP) ? scnt : LCAP;

    hist[tid] = 0;
    __syncthreads();
    for (int i = tid; i < n; i += 256) {
        uint32_t k = lkey[i];
        if ((k >> 24) == (uint32_t)sbin0) atomicAdd(&hist[(k >> 16) & 255u], 1);
    }
    __syncthreads();
    if (tid < 32) {
        int b0 = 248 - 8 * tid;
        int h[8], part = 0;
        #pragma unroll
        for (int q = 0; q < 8; q++) { h[q] = hist[b0 + q]; part += h[q]; }
        int inc = part;
        #pragma unroll
        for (int o = 1; o < 32; o <<= 1) {
            int t = __shfl_up_sync(0xffffffffu, inc, o);
            if (tid >= o) inc += t;
        }
        int pre = inc - part;
        if (pre < rem0 && rem0 <= inc) {
            int c = pre;
            #pragma unroll
            for (int q = 7; q >= 0; q--) {
                int nb = c + h[q];
                if (nb >= rem0) { sbin1 = b0 + q; srem1 = rem0 - c; break; }
                c = nb;
            }
        }
    }
    if (tid == 0) sfin = 0;
    __syncthreads();
    const uint32_t prefix16 = ((uint32_t)sbin0 << 8) | (uint32_t)sbin1;

    for (int i = tid; i < n; i += 256) {
        uint32_t k = lkey[i];
        if ((k >> 16) >= prefix16) {
            int p = atomicAdd(&sfin, 1);
            if (p < FCAP) { fkey[p] = k; fidx[p] = (int)lidx[i]; }
        }
    }
    __syncthreads();
    const int m = (sfin < FCAP) ? sfin : FCAP;

    if (tid < m) {
        uint32_t k = fkey[tid]; int ix = fidx[tid];
        int r = 0;
        for (int j = 0; j < m; j++) {
            uint32_t kj = fkey[j];
            if (kj > k || (kj == k && fidx[j] < ix)) r++;
        }
        if (r < FCAP) { svals[r] = key2f(k); sidxs[r] = ix; }
    }
    __syncthreads();

    if (tid == 0) {
        float t32 = svals[TOPK - 1];
        float hi = t32 + DELTA, lo = t32 - DELTA;
        int d = 0;
        while (d < TOPK && svals[d] > hi) d++;
        int u = 0;
        while (d + u < m && svals[d + u] >= lo) u++;
        sd = d; su = u;
    }
    __syncthreads();
    const int d = sd, u = su;
    if (u > 0 && d < TOPK) {
        const float* hrow = hs + (size_t)row * HDIM;
        const float inr = g_invn[row];
        for (int p = d + wid; p < d + u; p += 8) {
            const float* hc = hs + (size_t)sidxs[p] * HDIM;
            float acc = 0.f;
            for (int q = lid; q < HDIM; q += 32) acc = fmaf(hrow[q], hc[q], acc);
            #pragma unroll
            for (int o = 16; o; o >>= 1) acc += __shfl_down_sync(0xffffffffu, acc, o);
            if (lid == 0) exv[p] = acc * inr * g_invn[sidxs[p]];
        }
        __syncthreads();
        if (tid == 0) {
            float cv[FCAP]; int ci[FCAP]; bool used[FCAP];
            for (int p = 0; p < u; p++) { cv[p] = exv[d + p]; ci[p] = sidxs[d + p]; used[p] = false; }
            int pick = TOPK - d;
            if (pick > u) pick = u;
            for (int s = 0; s < pick; s++) {
                float bv = NEGINF; int bp = -1;
                for (int p = 0; p < u; p++)
                    if (!used[p] && (bp < 0 || cv[p] > bv)) { bv = cv[p]; bp = p; }
                used[bp] = true;
                svals[d + s] = bv; sidxs[d + s] = ci[bp];
            }
        }
        __syncthreads();
    }

    if (tid < TOPK) {
        float v = svals[tid];
        float mx = v;
        #pragma unroll
        for (int o = 16; o; o >>= 1) mx = fmaxf(mx, __shfl_xor_sync(0xffffffffu, mx, o));
        float e = isfinite(v) ? __expf(v - mx) : 0.f;
        float s = e;
        #pragma unroll
        for (int o = 16; o; o >>= 1) s += __shfl_xor_sync(0xffffffffu, s, o);
        float w = (s > 0.f) ? e / s : 0.f;
        g_topw[row * TOPK + tid] = w;
        g_topidx[row * TOPK + tid] = sidxs[tid];
    }
}

// ==================== K4: cross (fp16 gather from g_hi) + gate + residual ====================
__global__ __launch_bounds__(256) void cross_gate_kernel(const float* __restrict__ hs,
                                                         const float* __restrict__ gw,
                                                         const float* __restrict__ gb,
                                                         float* __restrict__ out) {
    const int row = blockIdx.x;
    const int tid = threadIdx.x;
    __shared__ float swg[TOPK];
    __shared__ uint32_t koff[TOPK];    // rb*TILE_ELEMS + rr*64 (fits 32 bits: < 16.8M)
    __shared__ int   kmsk[TOPK];
    __shared__ float red[8];
    __shared__ float gsh;
    if (tid < TOPK) {
        swg[tid] = g_topw[row * TOPK + tid];
        int r = g_topidx[row * TOPK + tid];
        int rb = r >> 7, rr = r & 127;
        koff[tid] = (uint32_t)(rb * TILE_ELEMS + rr * 64);
        kmsk[tid] = (rr & 7) << 4;
    }
    __syncthreads();

    const size_t kcstride = (size_t)NRB * TILE_ELEMS;
    float cr[HDIM / 256];
    float p = 0.f;
    #pragma unroll
    for (int u = 0; u < HDIM / 256; u++) {
        int c = tid + u * 256;
        const __half* hb = g_hi + (size_t)(c >> 6) * kcstride;
        const int cc2 = (c & 63) << 1;
        float acc = 0.f;
        #pragma unroll
        for (int k = 0; k < TOPK; k++) {
            uint32_t idx = koff[k] + (uint32_t)((cc2 ^ kmsk[k]) >> 1);
            acc = fmaf(swg[k], __half2float(hb[idx]), acc);
        }
        cr[u] = acc;
        float h = hs[(size_t)row * HDIM + c];
        p = fmaf(gw[c], h, p);
        p = fmaf(gw[HDIM + c], acc, p);
    }
    for (int o = 16; o; o >>= 1) p += __shfl_down_sync(0xffffffffu, p, o);
    if ((tid & 31) == 0) red[tid >> 5] = p;
    __syncthreads();
    if (tid == 0) {
        float v = 0.f;
        for (int i = 0; i < 8; i++) v += red[i];
        gsh = 1.f / (1.f + __expf(-(v + gb[0])));
    }
    __syncthreads();
    float g = gsh;
    #pragma unroll
    for (int u = 0; u < HDIM / 256; u++) {
        int c = tid + u * 256;
        float h = hs[(size_t)row * HDIM + c];
        out[(size_t)row * HDIM + c] = h + g * cr[u];
    }
}

// ==================== launch ====================
extern "C" void kernel_launch(void* const* d_in, const int* in_sizes, int n_in,
                              void* d_out, int out_size) {
    const float* hs  = (const float*)d_in[0];
    const int*   msk = (const int*)d_in[1];
    const float* gw  = (const float*)d_in[2];
    const float* gb  = (const float*)d_in[3];
    float* out       = (float*)d_out;

    static int smem_set = 0;
    if (!smem_set) {
        cudaFuncSetAttribute(simgemm_mma, cudaFuncAttributeMaxDynamicSharedMemorySize, SMEM_TOTAL);
        smem_set = 1;
    }

    prep_norms_kernel<<<BDIM, 256>>>(hs);
    dim3 grid(NRB, NRB);
    simgemm_mma<<<grid, 256, SMEM_TOTAL>>>(msk);
    topk_kernel<<<BDIM, 256>>>(hs);
    cross_gate_kernel<<<BDIM, 256>>>(hs, gw, gb, out);
}

// round 15
// speedup vs baseline: 1.3498x; 1.0581x over previous
#include <cuda_runtime.h>
#include <cuda_fp16.h>
#include <math.h>
#include <stdint.h>

#define BDIM 8192
#define HDIM 2048
#define TOPK 32
#define CAND 48
#define LCAP 3072
#define FCAP 128
#define DELTA 5e-5f
#define NEGINF (-INFINITY)

// ---- GEMM tiling ----
#define KCHUNK 64
#define NKC (HDIM / KCHUNK)
#define TILE_M 128
#define NRB (BDIM / TILE_M)
#define TILE_ELEMS (TILE_M * KCHUNK)
#define TILE_BYTES (TILE_ELEMS * 2)
#define STAGES 3
#define STAGE_BYTES (2 * TILE_BYTES)
#define SMEM_TOTAL (STAGES * STAGE_BYTES)

// ---- device scratch ----
__device__ float g_sim[(size_t)BDIM * BDIM];
__device__ float g_invn[BDIM];
__device__ int   g_topidx[BDIM * TOPK];
__device__ float g_topw[BDIM * TOPK];
__device__ __half g_hi[(size_t)NKC * NRB * TILE_ELEMS];

// ==================== asm helpers ====================
__device__ __forceinline__ uint32_t smem_u32(const void* p) {
    uint32_t a;
    asm("{ .reg .u64 t; cvta.to.shared.u64 t, %1; cvt.u32.u64 %0, t; }" : "=r"(a) : "l"(p));
    return a;
}

#define CP16(dst, src) \
    asm volatile("cp.async.cg.shared.global [%0], [%1], 16;" :: "r"(dst), "l"(src) : "memory")
#define CPCOMMIT() asm volatile("cp.async.commit_group;" ::: "memory")
#define CPWAIT1()  asm volatile("cp.async.wait_group 1;" ::: "memory")
#define CPWAIT0()  asm volatile("cp.async.wait_group 0;" ::: "memory")

#define LDSM4(r0, r1, r2, r3, addr) \
    asm volatile("ldmatrix.sync.aligned.m8n8.x4.shared.b16 {%0,%1,%2,%3}, [%4];" \
        : "=r"(r0), "=r"(r1), "=r"(r2), "=r"(r3) : "r"(addr))

#define MMA16816(d, a, b) \
    asm volatile("mma.sync.aligned.m16n8k16.row.col.f32.f16.f16.f32 " \
        "{%0,%1,%2,%3}, {%4,%5,%6,%7}, {%8,%9}, {%0,%1,%2,%3};" \
        : "+f"((d)[0]), "+f"((d)[1]), "+f"((d)[2]), "+f"((d)[3]) \
        : "r"((a)[0]), "r"((a)[1]), "r"((a)[2]), "r"((a)[3]), "r"((b)[0]), "r"((b)[1]))

// ==================== K0: fused norms + fp16 swizzled prep (one block per row) ====================
__global__ __launch_bounds__(256) void prep_norms_kernel(const float* __restrict__ hs) {
    const int r = blockIdx.x;
    const int tid = threadIdx.x;
    const float* p = hs + (size_t)r * HDIM;
    const int rb = r >> 7, rr = r & 127;
    float ssq = 0.f;

    #pragma unroll
    for (int half = 0; half < 2; half++) {
        int k4 = tid * 4 + half * 1024;
        float4 v = *(const float4*)(p + k4);
        float vv[4] = {v.x, v.y, v.z, v.w};
        int kc = k4 >> 6;
        size_t base = ((size_t)(kc * NRB + rb)) * TILE_ELEMS;
        #pragma unroll
        for (int j = 0; j < 4; j++) {
            float f = vv[j];
            ssq = fmaf(f, f, ssq);
            int c = (k4 + j) & 63;
            uint32_t off = (uint32_t)(rr * 128 + c * 2);
            uint32_t sw  = (off ^ (((uint32_t)(rr & 7)) << 4)) >> 1;
            g_hi[base + sw] = __float2half(f);
        }
    }

    __shared__ float red[8];
    for (int o = 16; o; o >>= 1) ssq += __shfl_down_sync(0xffffffffu, ssq, o);
    if ((tid & 31) == 0) red[tid >> 5] = ssq;
    __syncthreads();
    if (tid == 0) {
        float v = 0.f;
        for (int i = 0; i < 8; i++) v += red[i];
        g_invn[r] = 1.0f / fmaxf(sqrtf(v), 1e-12f);
    }
}

// ==================== K2: sim ~= H H^T via fp16 mma.sync, symmetric ====================
__global__ __launch_bounds__(256, 2) void simgemm_mma(const int* __restrict__ mask) {
    const int bj = blockIdx.x, bi = blockIdx.y;
    if (bi > bj) return;
    extern __shared__ __align__(128) char smem[];
    const uint32_t sbase = smem_u32(smem);
    const int tid = threadIdx.x;
    const int lane = tid & 31, wid = tid >> 5;
    const int wm = wid & 1, wn = wid >> 1;

    float acc[4][4][4];
    #pragma unroll
    for (int a = 0; a < 4; a++)
        #pragma unroll
        for (int b = 0; b < 4; b++)
            #pragma unroll
            for (int c = 0; c < 4; c++) acc[a][b][c] = 0.f;

    const __half* baseA = g_hi + (size_t)bi * TILE_ELEMS;
    const __half* baseB = g_hi + (size_t)bj * TILE_ELEMS;
    const size_t kc_stride = (size_t)NRB * TILE_ELEMS;

    const int rbase = (lane & 7) + ((lane >> 3) & 1) * 8;
    const int csel  = lane >> 4;

    auto issue = [&](int kc, int s) {
        uint32_t sb = sbase + s * STAGE_BYTES;
        const char* sa  = (const char*)(baseA + (size_t)kc * kc_stride);
        const char* sbp = (const char*)(baseB + (size_t)kc * kc_stride);
        #pragma unroll
        for (int i = 0; i < 4; i++) {
            uint32_t o = (uint32_t)(tid * 16 + i * 4096);
            CP16(sb + o, sa + o);
            CP16(sb + TILE_BYTES + o, sbp + o);
        }
        CPCOMMIT();
    };

    issue(0, 0);
    issue(1, 1);

    for (int kc = 0; kc < NKC; kc++) {
        CPWAIT1();
        __syncthreads();
        if (kc + 2 < NKC) issue(kc + 2, (kc + 2) % STAGES);

        uint32_t sb = sbase + (kc % STAGES) * STAGE_BYTES;
        #pragma unroll
        for (int k16 = 0; k16 < 4; k16++) {
            uint32_t ah[4][4], bh[4][2];
            #pragma unroll
            for (int mt = 0; mt < 4; mt++) {
                int row = wm * 64 + mt * 16 + rbase;
                uint32_t off = (uint32_t)(row * 128 + (((k16 * 2 + csel) ^ (row & 7)) * 16));
                LDSM4(ah[mt][0], ah[mt][1], ah[mt][2], ah[mt][3], sb + off);
            }
            #pragma unroll
            for (int p = 0; p < 2; p++) {
                int row = wn * 32 + p * 16 + rbase;
                uint32_t off = (uint32_t)(row * 128 + (((k16 * 2 + csel) ^ (row & 7)) * 16));
                uint32_t r0, r1, r2, r3;
                LDSM4(r0, r1, r2, r3, sb + TILE_BYTES + off);
                bh[2*p][0] = r0; bh[2*p][1] = r2; bh[2*p+1][0] = r1; bh[2*p+1][1] = r3;
            }
            #pragma unroll
            for (int mt = 0; mt < 4; mt++)
                #pragma unroll
                for (int nt = 0; nt < 4; nt++)
                    MMA16816(acc[mt][nt], ah[mt], bh[nt]);
        }
    }
    CPWAIT0();

    const int i0 = bi * 128 + wm * 64;
    const int j0 = bj * 128 + wn * 32;
    const int grp = lane >> 2, qd = lane & 3;
    #pragma unroll
    for (int mt = 0; mt < 4; mt++) {
        #pragma unroll
        for (int half = 0; half < 2; half++) {
            int row = i0 + mt * 16 + grp + half * 8;
            float sa = g_invn[row];
            int mr = mask[row];
            #pragma unroll
            for (int nt = 0; nt < 4; nt++) {
                int col = j0 + nt * 8 + qd * 2;
                float v0 = acc[mt][nt][half * 2 + 0] * sa * g_invn[col];
                float v1 = acc[mt][nt][half * 2 + 1] * sa * g_invn[col + 1];
                float2 o;
                o.x = (row == col     || mask[col]     == 0) ? NEGINF : v0;
                o.y = (row == col + 1 || mask[col + 1] == 0) ? NEGINF : v1;
                *(float2*)(g_sim + (size_t)row * BDIM + col) = o;
                if (bi != bj) {
                    g_sim[(size_t)col * BDIM + row]       = mr ? v0 : NEGINF;
                    g_sim[(size_t)(col + 1) * BDIM + row] = mr ? v1 : NEGINF;
                }
            }
        }
    }
}

// ==================== K3: per-row top-32, radix select + windowed fixup (R10 verbatim) ====================
__device__ __forceinline__ uint32_t f2key(float f) {
    uint32_t b = __float_as_uint(f);
    return (b & 0x80000000u) ? ~b : (b | 0x80000000u);
}
__device__ __forceinline__ float key2f(uint32_t k) {
    return __uint_as_float((k & 0x80000000u) ? (k & 0x7FFFFFFFu) : ~k);
}

__global__ __launch_bounds__(256) void topk_kernel(const float* __restrict__ hs) {
    __shared__ int whist[8][256];
    __shared__ int hist[256];
    __shared__ int sbin0, srem0, sbin1, srem1, scnt, sfin, sd, su;
    __shared__ uint32_t lkey[LCAP];
    __shared__ uint16_t lidx[LCAP];
    __shared__ uint32_t fkey[FCAP];
    __shared__ int      fidx[FCAP];
    __shared__ float svals[FCAP];
    __shared__ int   sidxs[FCAP];
    __shared__ float exv[FCAP];
    const int row = blockIdx.x;
    const int tid = threadIdx.x, wid = tid >> 5, lid = tid & 31;
    const float* sp = g_sim + (size_t)row * BDIM;

    {
        int* wh = &whist[0][0];
        for (int i = tid; i < 8 * 256; i += 256) wh[i] = 0;
    }
    __syncthreads();
    for (int c0 = tid * 4; c0 < BDIM; c0 += 1024) {
        float4 v = *(const float4*)(sp + c0);
        const float* vp = &v.x;
        #pragma unroll
        for (int j = 0; j < 4; j++) {
            uint32_t bin = f2key(vp[j]) >> 24;
            uint32_t mg = __match_any_sync(0xffffffffu, bin);
            if (lid == __ffs(mg) - 1) whist[wid][bin] += __popc(mg);
        }
    }
    __syncthreads();
    {
        int t = 0;
        #pragma unroll
        for (int w = 0; w < 8; w++) t += whist[w][tid];
        hist[tid] = t;
    }
    __syncthreads();
    if (tid < 32) {
        int b0 = 248 - 8 * tid;
        int h[8], part = 0;
        #pragma unroll
        for (int q = 0; q < 8; q++) { h[q] = hist[b0 + q]; part += h[q]; }
        int inc = part;
        #pragma unroll
        for (int o = 1; o < 32; o <<= 1) {
            int t = __shfl_up_sync(0xffffffffu, inc, o);
            if (tid >= o) inc += t;
        }
        int pre = inc - part;
        if (pre < CAND && CAND <= inc) {
            int c = pre;
            #pragma unroll
            for (int q = 7; q >= 0; q--) {
                int nb = c + h[q];
                if (nb >= CAND) { sbin0 = b0 + q; srem0 = CAND - c; break; }
                c = nb;
            }
        }
    }
    if (tid == 0) scnt = 0;
    __syncthreads();
    const uint32_t bound0 = (uint32_t)sbin0 << 24;
    const int rem0 = srem0;

    for (int c0 = tid * 4; c0 < BDIM; c0 += 1024) {
        float4 v = *(const float4*)(sp + c0);
        const float* vp = &v.x;
        #pragma unroll
        for (int j = 0; j < 4; j++) {
            uint32_t k = f2key(vp[j]);
            bool pred = (k >= bound0);
            uint32_t bal = __ballot_sync(0xffffffffu, pred);
            if (bal) {
                int leader = __ffs(bal) - 1;
                int b0v = 0;
                if (lid == leader) b0v = atomicAdd(&scnt, __popc(bal));
                b0v = __shfl_sync(0xffffffffu, b0v, leader);
                if (pred) {
                    int p = b0v + __popc(bal & ((1u << lid) - 1u));
                    if (p < LCAP) { lkey[p] = k; lidx[p] = (uint16_t)(c0 + j); }
                }
            }
        }
    }
    __syncthreads();
    const int n = (scnt < LCAP) ? scnt : LCAP;

    hist[tid] = 0;
    __syncthreads();
    for (int i = tid; i < n; i += 256) {
        uint32_t k = lkey[i];
        if ((k >> 24) == (uint32_t)sbin0) atomicAdd(&hist[(k >> 16) & 255u], 1);
    }
    __syncthreads();
    if (tid < 32) {
        int b0 = 248 - 8 * tid;
        int h[8], part = 0;
        #pragma unroll
        for (int q = 0; q < 8; q++) { h[q] = hist[b0 + q]; part += h[q]; }
        int inc = part;
        #pragma unroll
        for (int o = 1; o < 32; o <<= 1) {
            int t = __shfl_up_sync(0xffffffffu, inc, o);
            if (tid >= o) inc += t;
        }
        int pre = inc - part;
        if (pre < rem0 && rem0 <= inc) {
            int c = pre;
            #pragma unroll
            for (int q = 7; q >= 0; q--) {
                int nb = c + h[q];
                if (nb >= rem0) { sbin1 = b0 + q; srem1 = rem0 - c; break; }
                c = nb;
            }
        }
    }
    if (tid == 0) sfin = 0;
    __syncthreads();
    const uint32_t prefix16 = ((uint32_t)sbin0 << 8) | (uint32_t)sbin1;

    for (int i = tid; i < n; i += 256) {
        uint32_t k = lkey[i];
        if ((k >> 16) >= prefix16) {
            int p = atomicAdd(&sfin, 1);
            if (p < FCAP) { fkey[p] = k; fidx[p] = (int)lidx[i]; }
        }
    }
    __syncthreads();
    const int m = (sfin < FCAP) ? sfin : FCAP;

    if (tid < m) {
        uint32_t k = fkey[tid]; int ix = fidx[tid];
        int r = 0;
        for (int j = 0; j < m; j++) {
            uint32_t kj = fkey[j];
            if (kj > k || (kj == k && fidx[j] < ix)) r++;
        }
        if (r < FCAP) { svals[r] = key2f(k); sidxs[r] = ix; }
    }
    __syncthreads();

    if (tid == 0) {
        float t32 = svals[TOPK - 1];
        float hi = t32 + DELTA, lo = t32 - DELTA;
        int d = 0;
        while (d < TOPK && svals[d] > hi) d++;
        int u = 0;
        while (d + u < m && svals[d + u] >= lo) u++;
        sd = d; su = u;
    }
    __syncthreads();
    const int d = sd, u = su;
    if (u > 0 && d < TOPK) {
        const float* hrow = hs + (size_t)row * HDIM;
        const float inr = g_invn[row];
        for (int p = d + wid; p < d + u; p += 8) {
            const float* hc = hs + (size_t)sidxs[p] * HDIM;
            float acc = 0.f;
            for (int q = lid; q < HDIM; q += 32) acc = fmaf(hrow[q], hc[q], acc);
            #pragma unroll
            for (int o = 16; o; o >>= 1) acc += __shfl_down_sync(0xffffffffu, acc, o);
            if (lid == 0) exv[p] = acc * inr * g_invn[sidxs[p]];
        }
        __syncthreads();
        if (tid == 0) {
            float cv[FCAP]; int ci[FCAP]; bool used[FCAP];
            for (int p = 0; p < u; p++) { cv[p] = exv[d + p]; ci[p] = sidxs[d + p]; used[p] = false; }
            int pick = TOPK - d;
            if (pick > u) pick = u;
            for (int s = 0; s < pick; s++) {
                float bv = NEGINF; int bp = -1;
                for (int p = 0; p < u; p++)
                    if (!used[p] && (bp < 0 || cv[p] > bv)) { bv = cv[p]; bp = p; }
                used[bp] = true;
                svals[d + s] = bv; sidxs[d + s] = ci[bp];
            }
        }
        __syncthreads();
    }

    if (tid < TOPK) {
        float v = svals[tid];
        float mx = v;
        #pragma unroll
        for (int o = 16; o; o >>= 1) mx = fmaxf(mx, __shfl_xor_sync(0xffffffffu, mx, o));
        float e = isfinite(v) ? __expf(v - mx) : 0.f;
        float s = e;
        #pragma unroll
        for (int o = 16; o; o >>= 1) s += __shfl_xor_sync(0xffffffffu, s, o);
        float w = (s > 0.f) ? e / s : 0.f;
        g_topw[row * TOPK + tid] = w;
        g_topidx[row * TOPK + tid] = sidxs[tid];
    }
}

// ==================== K4: sparse cross + gate + residual (fp32, R10 verbatim) ====================
__global__ __launch_bounds__(256) void cross_gate_kernel(const float* __restrict__ hs,
                                                         const float* __restrict__ gw,
                                                         const float* __restrict__ gb,
                                                         float* __restrict__ out) {
    const int row = blockIdx.x;
    const int tid = threadIdx.x;
    __shared__ float sw[TOPK];
    __shared__ int   si[TOPK];
    __shared__ float red[8];
    __shared__ float gsh;
    if (tid < TOPK) { sw[tid] = g_topw[row * TOPK + tid]; si[tid] = g_topidx[row * TOPK + tid]; }
    __syncthreads();

    float cr[HDIM / 256];
    float p = 0.f;
    #pragma unroll
    for (int u = 0; u < HDIM / 256; u++) {
        int c = tid + u * 256;
        float acc = 0.f;
        #pragma unroll
        for (int k = 0; k < TOPK; k++)
            acc = fmaf(sw[k], hs[(size_t)si[k] * HDIM + c], acc);
        cr[u] = acc;
        float h = hs[(size_t)row * HDIM + c];
        p = fmaf(gw[c], h, p);
        p = fmaf(gw[HDIM + c], acc, p);
    }
    for (int o = 16; o; o >>= 1) p += __shfl_down_sync(0xffffffffu, p, o);
    if ((tid & 31) == 0) red[tid >> 5] = p;
    __syncthreads();
    if (tid == 0) {
        float v = 0.f;
        for (int i = 0; i < 8; i++) v += red[i];
        gsh = 1.f / (1.f + __expf(-(v + gb[0])));
    }
    __syncthreads();
    float g = gsh;
    #pragma unroll
    for (int u = 0; u < HDIM / 256; u++) {
        int c = tid + u * 256;
        float h = hs[(size_t)row * HDIM + c];
        out[(size_t)row * HDIM + c] = h + g * cr[u];
    }
}

// ==================== launch ====================
extern "C" void kernel_launch(void* const* d_in, const int* in_sizes, int n_in,
                              void* d_out, int out_size) {
    const float* hs  = (const float*)d_in[0];
    const int*   msk = (const int*)d_in[1];
    const float* gw  = (const float*)d_in[2];
    const float* gb  = (const float*)d_in[3];
    float* out       = (float*)d_out;

    static int smem_set = 0;
    if (!smem_set) {
        cudaFuncSetAttribute(simgemm_mma, cudaFuncAttributeMaxDynamicSharedMemorySize, SMEM_TOTAL);
        smem_set = 1;
    }

    prep_norms_kernel<<<BDIM, 256>>>(hs);
    dim3 grid(NRB, NRB);
    simgemm_mma<<<grid, 256, SMEM_TOTAL>>>(msk);
    topk_kernel<<<BDIM, 256>>>(hs);
    cross_gate_kernel<<<BDIM, 256>>>(hs, gw, gb, out);
}